// round 11
// baseline (speedup 1.0000x reference)
#include <cuda_runtime.h>
#include <cuda_bf16.h>
#include <math.h>

// ---------------------------------------------------------------------------
// GaussianSplattingDecoder.
// occ[v,c] = sum_g exp(-0.5*mahal)*opacity_g*sem_g[c] (dist^2 < R^2) + empty
// V = 100*100*8, N = 2048, C = 17.
// R10: two-level culling. Level 1: tile AABB (as before). Level 2: per-warp
// z-slab AABB (each warp owns a 4x4x2 voxel slab; z extent 0.91m vs 6.4m)
// prunes ~2x of the branchless inner-loop work. Lane remap: warp=(half,slab),
// lane=(lx,ly,zlo). Base: R9 (coalesced smem-transpose output, branchless
// inner loop, packed means cull, chunked staging, launch_bounds(256,5)).
// ---------------------------------------------------------------------------

#define N_GAUSS 2048
#define NUM_CLASSES 17
#define PROP_STRIDE 28      // 11 + 17
#define RADIUS_SQ 16.0f
#define CULL_MARGIN 0.01f
#define STAGE_CAP 256

// Packed means for culling: 32 KB, contiguous, L2-resident.
__device__ float4 g_means[N_GAUSS];

// Preprocessed gaussians: 7 float4s each (224 KB, L2-resident).
// f4[0] = {mx, my, mz, c00}
// f4[1] = {2*c01, 2*c02, c11, 2*c12}
// f4[2] = {c22, s0, s1, s2}     (s = opacity * semantics)
// f4[3..6] = {s3..s16, pad, pad}
__device__ float4 g_prep[N_GAUSS * 7];

__device__ __forceinline__ float softplus_stable(float x) {
    return fmaxf(x, 0.0f) + log1pf(expf(-fabsf(x)));
}

__global__ void prep_kernel(const float* __restrict__ props) {
    int g = blockIdx.x * blockDim.x + threadIdx.x;
    if (g >= N_GAUSS) return;
    const float* p = props + g * PROP_STRIDE;

    float s0 = fmaxf(softplus_stable(p[3]), 1e-4f);
    float s1 = fmaxf(softplus_stable(p[4]), 1e-4f);
    float s2 = fmaxf(softplus_stable(p[5]), 1e-4f);
    float a0 = 1.0f / fmaxf(s0 * s0, 1e-8f);
    float a1 = 1.0f / fmaxf(s1 * s1, 1e-8f);
    float a2 = 1.0f / fmaxf(s2 * s2, 1e-8f);

    float qw = p[6], qx = p[7], qy = p[8], qz = p[9];
    float inv_n = 1.0f / fmaxf(sqrtf(qw * qw + qx * qx + qy * qy + qz * qz), 1e-8f);
    qw *= inv_n; qx *= inv_n; qy *= inv_n; qz *= inv_n;

    float R00 = 1.0f - 2.0f * (qy * qy + qz * qz);
    float R01 = 2.0f * (qx * qy - qw * qz);
    float R02 = 2.0f * (qx * qz + qw * qy);
    float R10 = 2.0f * (qx * qy + qw * qz);
    float R11 = 1.0f - 2.0f * (qx * qx + qz * qz);
    float R12 = 2.0f * (qy * qz - qw * qx);
    float R20 = 2.0f * (qx * qz - qw * qy);
    float R21 = 2.0f * (qy * qz + qw * qx);
    float R22 = 1.0f - 2.0f * (qx * qx + qy * qy);

    float c00 = a0 * R00 * R00 + a1 * R01 * R01 + a2 * R02 * R02;
    float c01 = a0 * R00 * R10 + a1 * R01 * R11 + a2 * R02 * R12;
    float c02 = a0 * R00 * R20 + a1 * R01 * R21 + a2 * R02 * R22;
    float c11 = a0 * R10 * R10 + a1 * R11 * R11 + a2 * R12 * R12;
    float c12 = a0 * R10 * R20 + a1 * R11 * R21 + a2 * R12 * R22;
    float c22 = a0 * R20 * R20 + a1 * R21 * R21 + a2 * R22 * R22;

    float op = 1.0f / (1.0f + expf(-p[10]));

    g_means[g] = make_float4(p[0], p[1], p[2], 0.0f);

    float4* o = g_prep + g * 7;
    o[0] = make_float4(p[0], p[1], p[2], c00);
    o[1] = make_float4(2.0f * c01, 2.0f * c02, c11, 2.0f * c12);
    o[2] = make_float4(c22, op * p[11], op * p[12], op * p[13]);
    o[3] = make_float4(op * p[14], op * p[15], op * p[16], op * p[17]);
    o[4] = make_float4(op * p[18], op * p[19], op * p[20], op * p[21]);
    o[5] = make_float4(op * p[22], op * p[23], op * p[24], op * p[25]);
    o[6] = make_float4(op * p[26], op * p[27], 0.0f, 0.0f);
}

// Tile = 4x4x8 voxels. 256 threads = 8 warps.
// warp w: half = w>>2, slab = w&3 (z-slab of 2 cells).
// lane: lx = lane>>3, ly = (lane>>1)&3, lz = slab*2 + (lane&1).
__global__ __launch_bounds__(256, 5) void splat_kernel(
    const float* __restrict__ vox_coords, float* __restrict__ out)
{
    const int tid = threadIdx.x;
    const int lane = tid & 31;
    const int wrp = tid >> 5;          // 0..7
    const int half = wrp >> 2;
    const int slab = wrp & 3;
    const int tx = blockIdx.x * 4;
    const int ty = blockIdx.y * 4;
    const int lx = lane >> 3;          // 0..3
    const int ly = (lane >> 1) & 3;    // 0..3
    const int lz = slab * 2 + (lane & 1);  // 0..7
    const int vid = (lx * 4 + ly) * 8 + lz;   // 0..127, matches output layout
    const int v = ((tx + lx) * 100 + (ty + ly)) * 8 + lz;

    const float px = vox_coords[v * 3 + 0];
    const float py = vox_coords[v * 3 + 1];
    const float pz = vox_coords[v * 3 + 2];

    const float dxy = 80.0f / 99.0f;
    const float dz = 6.4f / 7.0f;
    const float bx0 = -40.0f + tx * dxy - CULL_MARGIN;
    const float bx1 = -40.0f + (tx + 3) * dxy + CULL_MARGIN;
    const float by0 = -40.0f + ty * dxy - CULL_MARGIN;
    const float by1 = -40.0f + (ty + 3) * dxy + CULL_MARGIN;
    const float bz0 = -1.0f - CULL_MARGIN;
    const float bz1 = 5.4f + CULL_MARGIN;
    // this warp's z-slab bounds (2 cells)
    const float sz0 = -1.0f + (slab * 2) * dz - CULL_MARGIN;
    const float sz1 = -1.0f + (slab * 2 + 1) * dz + CULL_MARGIN;

    __shared__ unsigned short s_list[N_GAUSS];          // 4 KB
    __shared__ float4 s_stage[STAGE_CAP * 7];           // 28 KB; reused for out
    __shared__ unsigned short s_wlist[8][STAGE_CAP];    // 4 KB per-warp sublists
    __shared__ int s_warp_sums[8];

    // --- Level-1 cull: tile AABB over packed means (contiguous lines) ---
    const int gbase = tid * 8;
    unsigned int hitmask = 0;
#pragma unroll
    for (int i = 0; i < 8; i++) {
        const float4 p0 = __ldg(g_means + gbase + i);
        float ex = fmaxf(fmaxf(bx0 - p0.x, p0.x - bx1), 0.0f);
        float ey = fmaxf(fmaxf(by0 - p0.y, p0.y - by1), 0.0f);
        float ez = fmaxf(fmaxf(bz0 - p0.z, p0.z - bz1), 0.0f);
        if (ex * ex + ey * ey + ez * ez < RADIUS_SQ) hitmask |= (1u << i);
    }
    int cnt = __popc(hitmask);

    // Deterministic order-preserving compaction
    int incl = cnt;
#pragma unroll
    for (int o = 1; o < 32; o <<= 1) {
        int vsh = __shfl_up_sync(0xffffffffu, incl, o);
        if (lane >= o) incl += vsh;
    }
    if (lane == 31) s_warp_sums[wrp] = incl;
    __syncthreads();
    int woff = 0, total = 0;
#pragma unroll
    for (int w = 0; w < 8; w++) {
        int ws = s_warp_sums[w];
        if (w < wrp) woff += ws;
        total += ws;
    }
    int offset = woff + incl - cnt;
    unsigned int mm = hitmask;
    while (mm) {
        int i = __ffs(mm) - 1;
        mm &= mm - 1;
        s_list[offset++] = (unsigned short)(gbase + i);
    }
    __syncthreads();

    // --- Chunked: stage, level-2 z-slab cull, accumulate ---
    float acc[NUM_CLASSES];
#pragma unroll
    for (int c = 0; c < NUM_CLASSES; c++) acc[c] = 0.0f;

    for (int base = 0; base < total; base += STAGE_CAP) {
        const int nc = min(STAGE_CAP, total - base);

        // cooperative copy: 7 float4s per survivor
        for (int t = tid; t < nc * 7; t += 256) {
            const int k = t / 7, j = t - k * 7;
            s_stage[k * 7 + j] = __ldg(g_prep + (int)s_list[base + k] * 7 + j);
        }
        __syncthreads();

        // Level-2: per-warp z-slab cull of staged chunk (order-preserving)
        int nsub = 0;
        for (int k0 = 0; k0 < nc; k0 += 32) {
            const int k = k0 + lane;
            bool hit = false;
            if (k < nc) {
                const float* mp = (const float*)(s_stage + k * 7);
                float mx = mp[0], my = mp[1], mz = mp[2];
                float ex = fmaxf(fmaxf(bx0 - mx, mx - bx1), 0.0f);
                float ey = fmaxf(fmaxf(by0 - my, my - by1), 0.0f);
                float ez = fmaxf(fmaxf(sz0 - mz, mz - sz1), 0.0f);
                hit = (ex * ex + ey * ey + ez * ez) < RADIUS_SQ;
            }
            unsigned int bm = __ballot_sync(0xffffffffu, hit);
            if (hit) {
                int pos = nsub + __popc(bm & ((1u << lane) - 1));
                s_wlist[wrp][pos] = (unsigned short)k;
            }
            nsub += __popc(bm);
        }
        __syncwarp();

        // split this warp's sublist between the two halves
        const int mid = nsub >> 1;
        const int t0 = half ? mid : 0;
        const int t1 = half ? nsub : mid;

#pragma unroll 4
        for (int t = t0; t < t1; t++) {
            const int k = (int)s_wlist[wrp][t];
            const float4* P = s_stage + k * 7;
            const float4 p0 = P[0];
            const float d0 = px - p0.x;
            const float d1 = py - p0.y;
            const float d2 = pz - p0.z;
            const bool inside = (d0 * d0 + d1 * d1 + d2 * d2) < RADIUS_SQ;
            const float4 p1 = P[1];
            const float4 p2 = P[2];
            float mahal = p0.w * d0 * d0 + p1.z * d1 * d1 + p2.x * d2 * d2
                        + p1.x * d0 * d1 + p1.y * d0 * d2 + p1.w * d1 * d2;
            float w = inside ? __expf(-0.5f * mahal) : 0.0f;
            acc[0] += w * p2.y;  acc[1] += w * p2.z;  acc[2] += w * p2.w;
            {
                const float4 s = P[3];
                acc[3] += w * s.x; acc[4] += w * s.y;
                acc[5] += w * s.z; acc[6] += w * s.w;
            }
            {
                const float4 s = P[4];
                acc[7] += w * s.x; acc[8] += w * s.y;
                acc[9] += w * s.z; acc[10] += w * s.w;
            }
            {
                const float4 s = P[5];
                acc[11] += w * s.x; acc[12] += w * s.y;
                acc[13] += w * s.z; acc[14] += w * s.w;
            }
            {
                const float4 s = P[6];
                acc[15] += w * s.x; acc[16] += w * s.y;
            }
        }
        __syncthreads();   // before next chunk overwrites s_stage
    }

    // --- Combine halves + coalesced output via smem transpose ---
    float* s_out = (float*)s_stage;
    float* s_part = s_out + 128 * NUM_CLASSES;

    if (half) {
#pragma unroll
        for (int c = 0; c < NUM_CLASSES; c++)
            s_part[vid * NUM_CLASSES + c] = acc[c];
    }
    __syncthreads();
    if (!half) {
#pragma unroll
        for (int c = 0; c < NUM_CLASSES; c++)
            acc[c] += s_part[vid * NUM_CLASSES + c];

        // Empty term: center=(0,0,2.2), inv=(1/1600,1/1600,1/10.24)
        const float de2 = pz - 2.2f;
        const float me = px * px * (1.0f / 1600.0f)
                       + py * py * (1.0f / 1600.0f)
                       + de2 * de2 * (1.0f / 10.24f);
        acc[0] += 0.1f * __expf(-0.5f * me) * 5.0f;

#pragma unroll
        for (int c = 0; c < NUM_CLASSES; c++)
            s_out[vid * NUM_CLASSES + c] = acc[c];
    }
    __syncthreads();

    // Cooperative coalesced store: for fixed lx, 544 contiguous gmem floats.
    {
        const float4* s4 = (const float4*)s_out;
        for (int t4 = tid; t4 < 544; t4 += 256) {
            const int lxb = t4 / 136;
            const int j4 = t4 - lxb * 136;
            float4* dst = (float4*)(out + ((size_t)((tx + lxb) * 100 + ty) * 8) * NUM_CLASSES);
            dst[j4] = s4[lxb * 136 + j4];
        }
    }
}

extern "C" void kernel_launch(void* const* d_in, const int* in_sizes, int n_in,
                              void* d_out, int out_size) {
    const float* props = (const float*)d_in[0];
    const float* vox   = (const float*)d_in[1];
    if (n_in >= 2 && in_sizes[0] == 100 * 100 * 8 * 3 &&
        in_sizes[1] == N_GAUSS * PROP_STRIDE) {
        const float* t = props; props = vox; vox = t;
    }
    float* out = (float*)d_out;

    prep_kernel<<<64, 32>>>(props);
    splat_kernel<<<dim3(25, 25), 256>>>(vox, out);
}

// round 12
// speedup vs baseline: 1.1450x; 1.1450x over previous
#include <cuda_runtime.h>
#include <cuda_bf16.h>
#include <math.h>

// ---------------------------------------------------------------------------
// GaussianSplattingDecoder.
// occ[v,c] = sum_g exp(-0.5*mahal)*opacity_g*sem_g[c] (dist^2 < R^2) + empty
// V = 100*100*8, N = 2048, C = 17.
// R11: revert R10 slab cull (regressed). Back to R9 structure + packed
// fma.rn.f32x2 accumulate: semantics laid out as 8 aligned (f32,f32) pairs
// + 1 scalar -> 8 FFMA2 + 1 FFMA instead of 17 FFMA (~20% fewer issue slots
// in the inner loop). Same 7 LDS.128/iter. Bitwise-identical math.
// ---------------------------------------------------------------------------

#define N_GAUSS 2048
#define NUM_CLASSES 17
#define PROP_STRIDE 28      // 11 + 17
#define RADIUS_SQ 16.0f
#define CULL_MARGIN 0.01f
#define STAGE_CAP 256

// Packed means for culling: 32 KB, contiguous, L2-resident.
__device__ float4 g_means[N_GAUSS];

// Preprocessed gaussians: 7 float4s each (224 KB, L2-resident).
// f4[0] = {mx, my, mz, c00}
// f4[1] = {2*c01, 2*c02, c11, 2*c12}
// f4[2] = {c22, s16, s0, s1}      (s = opacity * semantics)
// f4[3] = {s2, s3, s4, s5}
// f4[4] = {s6, s7, s8, s9}
// f4[5] = {s10, s11, s12, s13}
// f4[6] = {s14, s15, 0, 0}
__device__ float4 g_prep[N_GAUSS * 7];

#define FMA2(accp, pair, ww) \
    asm("fma.rn.f32x2 %0, %1, %2, %0;" : "+l"(accp) : "l"(pair), "l"(ww))
#define PACK2(dst, lo, hi) \
    asm("mov.b64 %0, {%1, %2};" : "=l"(dst) : "f"(lo), "f"(hi))
#define UNPACK2(lo, hi, src) \
    asm("mov.b64 {%0, %1}, %2;" : "=f"(lo), "=f"(hi) : "l"(src))

__device__ __forceinline__ float softplus_stable(float x) {
    return fmaxf(x, 0.0f) + log1pf(expf(-fabsf(x)));
}

__global__ void prep_kernel(const float* __restrict__ props) {
    int g = blockIdx.x * blockDim.x + threadIdx.x;
    if (g >= N_GAUSS) return;
    const float* p = props + g * PROP_STRIDE;

    float s0 = fmaxf(softplus_stable(p[3]), 1e-4f);
    float s1 = fmaxf(softplus_stable(p[4]), 1e-4f);
    float s2 = fmaxf(softplus_stable(p[5]), 1e-4f);
    float a0 = 1.0f / fmaxf(s0 * s0, 1e-8f);
    float a1 = 1.0f / fmaxf(s1 * s1, 1e-8f);
    float a2 = 1.0f / fmaxf(s2 * s2, 1e-8f);

    float qw = p[6], qx = p[7], qy = p[8], qz = p[9];
    float inv_n = 1.0f / fmaxf(sqrtf(qw * qw + qx * qx + qy * qy + qz * qz), 1e-8f);
    qw *= inv_n; qx *= inv_n; qy *= inv_n; qz *= inv_n;

    float R00 = 1.0f - 2.0f * (qy * qy + qz * qz);
    float R01 = 2.0f * (qx * qy - qw * qz);
    float R02 = 2.0f * (qx * qz + qw * qy);
    float R10 = 2.0f * (qx * qy + qw * qz);
    float R11 = 1.0f - 2.0f * (qx * qx + qz * qz);
    float R12 = 2.0f * (qy * qz - qw * qx);
    float R20 = 2.0f * (qx * qz - qw * qy);
    float R21 = 2.0f * (qy * qz + qw * qx);
    float R22 = 1.0f - 2.0f * (qx * qx + qy * qy);

    float c00 = a0 * R00 * R00 + a1 * R01 * R01 + a2 * R02 * R02;
    float c01 = a0 * R00 * R10 + a1 * R01 * R11 + a2 * R02 * R12;
    float c02 = a0 * R00 * R20 + a1 * R01 * R21 + a2 * R02 * R22;
    float c11 = a0 * R10 * R10 + a1 * R11 * R11 + a2 * R12 * R12;
    float c12 = a0 * R10 * R20 + a1 * R11 * R21 + a2 * R12 * R22;
    float c22 = a0 * R20 * R20 + a1 * R21 * R21 + a2 * R22 * R22;

    float op = 1.0f / (1.0f + expf(-p[10]));

    g_means[g] = make_float4(p[0], p[1], p[2], 0.0f);

    float4* o = g_prep + g * 7;
    o[0] = make_float4(p[0], p[1], p[2], c00);
    o[1] = make_float4(2.0f * c01, 2.0f * c02, c11, 2.0f * c12);
    o[2] = make_float4(c22, op * p[27], op * p[11], op * p[12]);
    o[3] = make_float4(op * p[13], op * p[14], op * p[15], op * p[16]);
    o[4] = make_float4(op * p[17], op * p[18], op * p[19], op * p[20]);
    o[5] = make_float4(op * p[21], op * p[22], op * p[23], op * p[24]);
    o[6] = make_float4(op * p[25], op * p[26], 0.0f, 0.0f);
}

// Tile = 4x4x8 voxels. 256 threads: tid&127 -> voxel, tid>>7 -> list half.
__global__ __launch_bounds__(256, 5) void splat_kernel(
    const float* __restrict__ vox_coords, float* __restrict__ out)
{
    const int tid = threadIdx.x;
    const int tx = blockIdx.x * 4;
    const int ty = blockIdx.y * 4;
    const int vtid = tid & 127;
    const int half = tid >> 7;
    const int lx = vtid >> 5;          // 0..3
    const int ly = (vtid >> 3) & 3;    // 0..3
    const int lz = vtid & 7;           // 0..7
    const int v = ((tx + lx) * 100 + (ty + ly)) * 8 + lz;

    const float px = vox_coords[v * 3 + 0];
    const float py = vox_coords[v * 3 + 1];
    const float pz = vox_coords[v * 3 + 2];

    const float dxy = 80.0f / 99.0f;
    const float bx0 = -40.0f + tx * dxy - CULL_MARGIN;
    const float bx1 = -40.0f + (tx + 3) * dxy + CULL_MARGIN;
    const float by0 = -40.0f + ty * dxy - CULL_MARGIN;
    const float by1 = -40.0f + (ty + 3) * dxy + CULL_MARGIN;
    const float bz0 = -1.0f - CULL_MARGIN;
    const float bz1 = 5.4f + CULL_MARGIN;

    __shared__ unsigned short s_list[N_GAUSS];   // 4 KB
    __shared__ float4 s_stage[STAGE_CAP * 7];    // 28 KB; aliased for output
    __shared__ int s_warp_sums[8];

    // --- Phase 1: AABB cull on packed means (32 KB contiguous) ---
    const int gbase = tid * 8;
    unsigned int hitmask = 0;
#pragma unroll
    for (int i = 0; i < 8; i++) {
        const float4 p0 = __ldg(g_means + gbase + i);
        float ex = fmaxf(fmaxf(bx0 - p0.x, p0.x - bx1), 0.0f);
        float ey = fmaxf(fmaxf(by0 - p0.y, p0.y - by1), 0.0f);
        float ez = fmaxf(fmaxf(bz0 - p0.z, p0.z - bz1), 0.0f);
        if (ex * ex + ey * ey + ez * ez < RADIUS_SQ) hitmask |= (1u << i);
    }
    int cnt = __popc(hitmask);

    // Deterministic order-preserving compaction
    const int lane = tid & 31, wid = tid >> 5;
    int incl = cnt;
#pragma unroll
    for (int o = 1; o < 32; o <<= 1) {
        int vsh = __shfl_up_sync(0xffffffffu, incl, o);
        if (lane >= o) incl += vsh;
    }
    if (lane == 31) s_warp_sums[wid] = incl;
    __syncthreads();
    int woff = 0, total = 0;
#pragma unroll
    for (int w = 0; w < 8; w++) {
        int ws = s_warp_sums[w];
        if (w < wid) woff += ws;
        total += ws;
    }
    int offset = woff + incl - cnt;
    unsigned int m = hitmask;
    while (m) {
        int i = __ffs(m) - 1;
        m &= m - 1;
        s_list[offset++] = (unsigned short)(gbase + i);
    }
    __syncthreads();

    // --- Phase 2/3 chunked: stage survivors, accumulate (branchless, f32x2) --
    unsigned long long accp[8];
#pragma unroll
    for (int i = 0; i < 8; i++) accp[i] = 0ull;   // == (0.0f, 0.0f)
    float acc16 = 0.0f;

    for (int base = 0; base < total; base += STAGE_CAP) {
        const int nc = min(STAGE_CAP, total - base);

        // cooperative copy: 7 float4s per survivor, spread across threads
        for (int t = tid; t < nc * 7; t += 256) {
            const int k = t / 7, j = t - k * 7;
            s_stage[k * 7 + j] = __ldg(g_prep + (int)s_list[base + k] * 7 + j);
        }
        __syncthreads();

        const int mid = nc >> 1;
        const int k0 = half ? mid : 0;
        const int k1 = half ? nc : mid;

#pragma unroll 4
        for (int k = k0; k < k1; k++) {
            const float4* P = s_stage + k * 7;
            const ulonglong2* Q = (const ulonglong2*)P;
            const float4 p0 = P[0];
            const float4 p1 = P[1];
            const ulonglong2 q2 = Q[2];     // (c22,s16) (s0,s1)
            float c22, s16;
            UNPACK2(c22, s16, q2.x);

            const float d0 = px - p0.x;
            const float d1 = py - p0.y;
            const float d2 = pz - p0.z;
            const bool inside = (d0 * d0 + d1 * d1 + d2 * d2) < RADIUS_SQ;
            float mahal = p0.w * d0 * d0 + p1.z * d1 * d1 + c22 * d2 * d2
                        + p1.x * d0 * d1 + p1.y * d0 * d2 + p1.w * d1 * d2;
            float w = inside ? __expf(-0.5f * mahal) : 0.0f;
            unsigned long long ww;
            PACK2(ww, w, w);

            FMA2(accp[0], q2.y, ww);
            {
                const ulonglong2 q = Q[3];
                FMA2(accp[1], q.x, ww);
                FMA2(accp[2], q.y, ww);
            }
            {
                const ulonglong2 q = Q[4];
                FMA2(accp[3], q.x, ww);
                FMA2(accp[4], q.y, ww);
            }
            {
                const ulonglong2 q = Q[5];
                FMA2(accp[5], q.x, ww);
                FMA2(accp[6], q.y, ww);
            }
            FMA2(accp[7], Q[6].x, ww);
            acc16 = fmaf(w, s16, acc16);
        }
        __syncthreads();   // before next chunk overwrites s_stage
    }

    // Unpack accumulators: classes 0..15 from pairs, 16 scalar.
    float acc[NUM_CLASSES];
#pragma unroll
    for (int i = 0; i < 8; i++) UNPACK2(acc[2 * i], acc[2 * i + 1], accp[i]);
    acc[16] = acc16;

    // --- Combine halves + coalesced output via smem transpose ---
    float* s_out = (float*)s_stage;
    float* s_part = s_out + 128 * NUM_CLASSES;

    if (half) {
#pragma unroll
        for (int c = 0; c < NUM_CLASSES; c++)
            s_part[vtid * NUM_CLASSES + c] = acc[c];
    }
    __syncthreads();
    if (!half) {
#pragma unroll
        for (int c = 0; c < NUM_CLASSES; c++)
            acc[c] += s_part[vtid * NUM_CLASSES + c];

        // Empty term: center=(0,0,2.2), inv=(1/1600,1/1600,1/10.24)
        const float de2 = pz - 2.2f;
        const float me = px * px * (1.0f / 1600.0f)
                       + py * py * (1.0f / 1600.0f)
                       + de2 * de2 * (1.0f / 10.24f);
        acc[0] += 0.1f * __expf(-0.5f * me) * 5.0f;

#pragma unroll
        for (int c = 0; c < NUM_CLASSES; c++)
            s_out[vtid * NUM_CLASSES + c] = acc[c];
    }
    __syncthreads();

    // Cooperative coalesced store: for fixed lx, 544 contiguous gmem floats.
    {
        const float4* s4 = (const float4*)s_out;
        for (int t4 = tid; t4 < 544; t4 += 256) {
            const int lxb = t4 / 136;
            const int j4 = t4 - lxb * 136;
            float4* dst = (float4*)(out + ((size_t)((tx + lxb) * 100 + ty) * 8) * NUM_CLASSES);
            dst[j4] = s4[lxb * 136 + j4];
        }
    }
}

extern "C" void kernel_launch(void* const* d_in, const int* in_sizes, int n_in,
                              void* d_out, int out_size) {
    const float* props = (const float*)d_in[0];
    const float* vox   = (const float*)d_in[1];
    if (n_in >= 2 && in_sizes[0] == 100 * 100 * 8 * 3 &&
        in_sizes[1] == N_GAUSS * PROP_STRIDE) {
        const float* t = props; props = vox; vox = t;
    }
    float* out = (float*)d_out;

    prep_kernel<<<64, 32>>>(props);
    splat_kernel<<<dim3(25, 25), 256>>>(vox, out);
}